// round 1
// baseline (speedup 1.0000x reference)
#include <cuda_runtime.h>
#include <math.h>

// FraudDetectionHybridModel — closed-form reduction of the quantum circuit.
//
// Per 2x2 patch with pixels t0..t3 (row-major):
//   feats = [cos t0, cos t0*cos t1, cos t0*cos t1*cos t2, cos t0*cos t1*cos t2*cos t3]
// (RZ(patch_params) only shifts phases -> no effect on <Z>; CNOT chain turns
//  independent product-state qubits into prefix-XOR parities -> prefix cos products.)
//
// out[b] = sigmoid( cos( sum_{p,w} feats[b,p,w] * W[p*4+w] ) ),  W = classifier_params[:784]

#define GRID14 14
#define NPATCH 196           // 14*14
#define THREADS 224          // 7 warps; threads 0..195 active

__global__ void __launch_bounds__(THREADS, 8)
fraud_kernel(const float* __restrict__ x,          // [B,784] (B,1,28,28 flattened)
             const float* __restrict__ w,          // [785], first 784 used
             float* __restrict__ out,              // [B]
             int B)
{
    const int b = blockIdx.x;
    if (b >= B) return;
    const int t = threadIdx.x;

    float acc = 0.0f;
    if (t < NPATCH) {
        const int i = t / GRID14;        // patch row
        const int j = t - i * GRID14;    // patch col
        const float* xb = x + (size_t)b * 784 + (2 * i) * 28 + 2 * j;

        // two aligned 8-byte loads: rows 2i and 2i+1 of this 2x2 patch
        const float2 r0 = *reinterpret_cast<const float2*>(xb);
        const float2 r1 = *reinterpret_cast<const float2*>(xb + 28);

        const float c0 = __cosf(r0.x);
        const float c1 = __cosf(r0.y);
        const float c2 = __cosf(r1.x);
        const float c3 = __cosf(r1.y);

        const float f0 = c0;
        const float f1 = f0 * c1;
        const float f2 = f1 * c2;
        const float f3 = f2 * c3;

        const float4 wv = *reinterpret_cast<const float4*>(w + t * 4);
        acc = fmaf(f0, wv.x, fmaf(f1, wv.y, fmaf(f2, wv.z, f3 * wv.w)));
    }

    // intra-warp tree reduce
    #pragma unroll
    for (int off = 16; off > 0; off >>= 1)
        acc += __shfl_down_sync(0xffffffffu, acc, off);

    __shared__ float warp_sum[THREADS / 32];
    const int wid = t >> 5;
    const int lane = t & 31;
    if (lane == 0) warp_sum[wid] = acc;
    __syncthreads();

    if (t == 0) {
        float a = warp_sum[0];
        #pragma unroll
        for (int k = 1; k < THREADS / 32; ++k) a += warp_sum[k];
        const float cv = cosf(a);                       // full-precision cos: |a| can be ~15
        out[b] = 1.0f / (1.0f + __expf(-cv));           // cv in [-1,1] -> __expf safe
    }
}

extern "C" void kernel_launch(void* const* d_in, const int* in_sizes, int n_in,
                              void* d_out, int out_size)
{
    const float* x = (const float*)d_in[0];   // [B,1,28,28]
    // d_in[1] = patch_params — provably unused (RZ is pure phase)
    const float* w = (const float*)d_in[2];   // [785]
    float* out = (float*)d_out;

    const int B = in_sizes[0] / 784;
    fraud_kernel<<<B, THREADS>>>(x, w, out, B);
}

// round 2
// speedup vs baseline: 1.3349x; 1.3349x over previous
#include <cuda_runtime.h>
#include <math.h>

// FraudDetectionHybridModel — closed-form quantum-circuit reduction.
// Per 2x2 patch (pixels t0..t3 row-major):
//   feats = prefix products of cos(t_k); RZ(params) is pure phase (unused).
// out[b] = sigmoid( cos( sum_{p,w} feats[b,p,w] * W[p*4+w] ) )
//
// Layout: one warp = half a batch image (49 "items"); item = 2 rows x 4 cols
// = two horizontally adjacent patches, loaded as two float4s.
// CTA = 256 threads = 8 warps = 4 batch elements. Grid = B/4 = 1024 (one wave).

#define NPAIRS_HALF 49   // 98 items per image, 49 per warp

__device__ __forceinline__ float pair_contrib(float4 top, float4 bot, int i, int c,
                                              const float* __restrict__ w)
{
    // patch A = (i, 2c): top.x,top.y,bot.x,bot.y ; patch B = (i, 2c+1)
    const float cA0 = __cosf(top.x), cA1 = __cosf(top.y);
    const float cA2 = __cosf(bot.x), cA3 = __cosf(bot.y);
    const float fA0 = cA0, fA1 = fA0 * cA1, fA2 = fA1 * cA2, fA3 = fA2 * cA3;

    const float cB0 = __cosf(top.z), cB1 = __cosf(top.w);
    const float cB2 = __cosf(bot.z), cB3 = __cosf(bot.w);
    const float fB0 = cB0, fB1 = fB0 * cB1, fB2 = fB1 * cB2, fB3 = fB2 * cB3;

    const int pa = (i * 14 + 2 * c) * 4;                 // weight offset of patch A
    const float4 wa = *reinterpret_cast<const float4*>(w + pa);
    const float4 wb = *reinterpret_cast<const float4*>(w + pa + 4);

    float r = fmaf(fA0, wa.x, fmaf(fA1, wa.y, fmaf(fA2, wa.z, fA3 * wa.w)));
    r = fmaf(fB0, wb.x, fmaf(fB1, wb.y, fmaf(fB2, wb.z, fmaf(fB3, wb.w, r))));
    return r;
}

__global__ void __launch_bounds__(256, 7)
fraud_kernel(const float* __restrict__ x,   // [B, 784]
             const float* __restrict__ w,   // [785]
             float* __restrict__ out,       // [B]
             int B)
{
    const int tid  = threadIdx.x;
    const int warp = tid >> 5;
    const int lane = tid & 31;

    int b = blockIdx.x * 4 + (warp >> 1);
    if (b >= B) b = B - 1;                    // safe duplicate work; store is guarded
    const int half = warp & 1;

    const float* xb = x + (size_t)b * 784;

    // item indices for this lane: p0 always active (lane < 49), p1 if lane < 17
    const int p0 = half * NPAIRS_HALF + lane;
    const int p1 = p0 + 32;
    const bool a1 = (lane < NPAIRS_HALF - 32);

    // ---- load phase (maximize MLP) ----
    const int i0 = p0 / 7, c0 = p0 % 7;
    const float* q0 = xb + i0 * 56 + c0 * 4;              // row 2*i0, col 4*c0
    const float4 t0 = *reinterpret_cast<const float4*>(q0);
    const float4 b0 = *reinterpret_cast<const float4*>(q0 + 28);

    int i1 = 0, c1 = 0;
    float4 t1 = make_float4(0.f, 0.f, 0.f, 0.f), b1 = t1;
    if (a1) {
        i1 = p1 / 7; c1 = p1 % 7;
        const float* q1 = xb + i1 * 56 + c1 * 4;
        t1 = *reinterpret_cast<const float4*>(q1);
        b1 = *reinterpret_cast<const float4*>(q1 + 28);
    }

    // ---- compute phase ----
    float acc = pair_contrib(t0, b0, i0, c0, w);
    if (a1) acc += pair_contrib(t1, b1, i1, c1, w);

    // ---- warp reduce (butterfly) ----
    #pragma unroll
    for (int off = 16; off > 0; off >>= 1)
        acc += __shfl_xor_sync(0xffffffffu, acc, off);

    __shared__ float wsum[8];
    if (lane == 0) wsum[warp] = acc;
    __syncthreads();

    if (warp == 0 && lane < 4) {
        const int ob = blockIdx.x * 4 + lane;
        if (ob < B) {
            const float a  = wsum[2 * lane] + wsum[2 * lane + 1];
            const float cv = cosf(a);                      // |a| can be ~40: full-precision
            out[ob] = 1.0f / (1.0f + __expf(-cv));
        }
    }
}

extern "C" void kernel_launch(void* const* d_in, const int* in_sizes, int n_in,
                              void* d_out, int out_size)
{
    const float* x = (const float*)d_in[0];   // [B,1,28,28]
    // d_in[1] = patch_params — provably unused (RZ is pure phase)
    const float* w = (const float*)d_in[2];   // [785]
    float* out = (float*)d_out;

    const int B = in_sizes[0] / 784;
    const int grid = (B + 3) / 4;
    fraud_kernel<<<grid, 256>>>(x, w, out, B);
}